// round 16
// baseline (speedup 1.0000x reference)
#include <cuda_runtime.h>
#include <cuda_bf16.h>
#include <cstdint>

#define S_LEN   2048
#define D_MODEL 1024
#define NHEAD   16
#define HDIM    64
#define BATCH   2
#define M_ROWS  (BATCH * S_LEN)   // 4096

// ---------------------------------------------------------------------------
// Scratch (device globals: allocation-free per harness rules)
// ---------------------------------------------------------------------------
__device__ float g_Q[BATCH * NHEAD * S_LEN * HDIM];   // [B*H, S, Hd]
__device__ float g_K[BATCH * NHEAD * S_LEN * HDIM];
__device__ float g_V[BATCH * NHEAD * S_LEN * HDIM];
__device__ float g_C[M_ROWS * D_MODEL];               // attention context [B*S, D]

__device__ __forceinline__ float ex2f_fast(float x) {
    float r;
    asm("ex2.approx.ftz.f32 %0, %1;" : "=f"(r) : "f"(x));
    return r;
}

__device__ __forceinline__ uint32_t smem_u32(const void* p) {
    return (uint32_t)__cvta_generic_to_shared(p);
}

// ldmatrix x4 (sm_75+, valid on compute_103 virtual target)
__device__ __forceinline__ void ldmx4(uint32_t* r, uint32_t addr) {
    asm volatile("ldmatrix.sync.aligned.m8n8.x4.shared.b16 {%0,%1,%2,%3}, [%4];"
                 : "=r"(r[0]), "=r"(r[1]), "=r"(r[2]), "=r"(r[3])
                 : "r"(addr));
}
__device__ __forceinline__ void ldmx4t(uint32_t* r, uint32_t addr) {
    asm volatile("ldmatrix.sync.aligned.m8n8.x4.trans.shared.b16 {%0,%1,%2,%3}, [%4];"
                 : "=r"(r[0]), "=r"(r[1]), "=r"(r[2]), "=r"(r[3])
                 : "r"(addr));
}

// bf16 HMMA m16n8k16 (sm_80+)
__device__ __forceinline__ void mma16816(float* d, const uint32_t* a,
                                         uint32_t b0, uint32_t b1) {
    asm volatile(
        "mma.sync.aligned.m16n8k16.row.col.f32.bf16.bf16.f32 "
        "{%0,%1,%2,%3}, {%4,%5,%6,%7}, {%8,%9}, {%0,%1,%2,%3};"
        : "+f"(d[0]), "+f"(d[1]), "+f"(d[2]), "+f"(d[3])
        : "r"(a[0]), "r"(a[1]), "r"(a[2]), "r"(a[3]), "r"(b0), "r"(b1));
}

// split a float4 into bf16 hi + bf16 residual lo, store as two bf162 pairs
__device__ __forceinline__ void split_store(void* hp, void* lp, float4 v) {
    __nv_bfloat162 h0 = __floats2bfloat162_rn(v.x, v.y);
    __nv_bfloat162 h1 = __floats2bfloat162_rn(v.z, v.w);
    __nv_bfloat162 l0 = __floats2bfloat162_rn(v.x - __low2float(h0),
                                              v.y - __high2float(h0));
    __nv_bfloat162 l1 = __floats2bfloat162_rn(v.z - __low2float(h1),
                                              v.w - __high2float(h1));
    ((__nv_bfloat162*)hp)[0] = h0; ((__nv_bfloat162*)hp)[1] = h1;
    ((__nv_bfloat162*)lp)[0] = l0; ((__nv_bfloat162*)lp)[1] = l1;
}

__device__ __forceinline__ void pack_hilo(float x, float y,
                                          uint32_t& hi, uint32_t& lo) {
    __nv_bfloat162 h = __floats2bfloat162_rn(x, y);
    __nv_bfloat162 l = __floats2bfloat162_rn(x - __low2float(h),
                                             y - __high2float(h));
    hi = *(uint32_t*)&h;
    lo = *(uint32_t*)&l;
}

// ---------------------------------------------------------------------------
// Tensor-core GEMM (HMMA bf16 split hi/lo, 3 terms):
//   C[4096,1024] = A[4096,1024] @ W[1024,1024]^T + bias
// Block 128x64, 256 threads (8 warps, warp grid 4x2, warp tile 32x32).
// 2 CTAs/SM (launch_bounds(256,2)): barrier/staging bubbles of one CTA are
// covered by the other CTA's MMA stream.
// MODE 0: QKV (blockIdx.z selects W/bias; scatter into [B*H,S,Hd])
// MODE 1: output projection (A = g_C, row-major out)
// ---------------------------------------------------------------------------
#define GROW 48                    // bytes per smem tile row (16 bf16 + pad)
#define GA   (128 * GROW)          // A matrix bytes per stage half (6144)
#define GB   (64 * GROW)           // B matrix bytes (3072)
#define GSTG (2 * GA + 2 * GB)     // Ahi, Alo, Bhi, Blo = 18432
#define GEMM_SMEM (2 * GSTG)       // 36864

template <int MODE>
__global__ __launch_bounds__(256, 2)
void gemm_mma(const float* __restrict__ A,
              const float* __restrict__ W0, const float* __restrict__ W1,
              const float* __restrict__ W2,
              const float* __restrict__ b0, const float* __restrict__ b1,
              const float* __restrict__ b2,
              float* __restrict__ OutExt)
{
    extern __shared__ char gsm[];

    const float* W;
    const float* bias;
    float* out;
    const float* Ause;
    if (MODE == 0) {
        int z = blockIdx.z;
        W    = (z == 0) ? W0 : (z == 1) ? W1 : W2;
        bias = (z == 0) ? b0 : (z == 1) ? b1 : b2;
        out  = (z == 0) ? g_Q : (z == 1) ? g_K : g_V;
        Ause = A;
    } else {
        W = W0; bias = b0; out = OutExt; Ause = g_C;
    }

    const int tid  = threadIdx.x;
    const int lane = tid & 31;
    const int wid  = tid >> 5;          // 0..7
    const int wm   = wid >> 1;          // 0..3  (32-row group)
    const int wn   = wid & 1;           // 0..1  (32-col group)
    const int m0   = blockIdx.y * 128;
    const int n0   = blockIdx.x * 64;

    // ---- staging coords
    // A: thread -> row = tid>>1, two float4 at cols (tid&1)*8, +4
    const int arow = tid >> 1;
    const int acol = (tid & 1) * 8;
    const float* Aptr = Ause + (size_t)(m0 + arow) * D_MODEL + acol;
    const uint32_t soffA = (uint32_t)(arow * GROW + acol * 2);
    // B: thread -> row = tid>>2, one float4 at col (tid&3)*4
    const int brow = tid >> 2;
    const int bseg = (tid & 3) * 4;
    const float* Bptr = W + (size_t)(n0 + brow) * D_MODEL + bseg;
    const uint32_t soffB = (uint32_t)(brow * GROW + bseg * 2);

    const uint32_t sb = smem_u32(gsm);

    // ---- ldmatrix read offsets
    const uint32_t aoff = (uint32_t)((wm * 32 + (lane & 15)) * GROW
                                     + (lane >> 4) * 16);
    const uint32_t boff = (uint32_t)((wn * 32 + (lane & 7) + ((lane >> 4) << 3)) * GROW
                                     + ((lane >> 3) & 1) * 16);

    auto stage = [&](uint32_t base, float4 a0, float4 a1, float4 w) {
        split_store(gsm + base + soffA,      gsm + base + GA + soffA,      a0);
        split_store(gsm + base + soffA + 8,  gsm + base + GA + soffA + 8,  a1);
        split_store(gsm + base + 2 * GA + soffB,
                    gsm + base + 2 * GA + GB + soffB, w);
    };

    // ---- prologue: stage chunk 0 into buffer 0
    {
        float4 a0 = *(const float4*)(Aptr);
        float4 a1 = *(const float4*)(Aptr + 4);
        float4 w  = *(const float4*)(Bptr);
        stage(0, a0, a1, w);
    }
    __syncthreads();

    float acc[2][4][4];
#pragma unroll
    for (int i = 0; i < 2; i++)
#pragma unroll
        for (int j = 0; j < 4; j++)
#pragma unroll
            for (int k = 0; k < 4; k++) acc[i][j][k] = 0.0f;

    const int NC = D_MODEL / 16;   // 64
    for (int c = 0; c < NC; c++) {
        const uint32_t st  = sb + (uint32_t)(c & 1) * GSTG;
        const uint32_t stg = (uint32_t)((c + 1) & 1) * GSTG;

        float4 a0, a1, w;
        if (c < NC - 1) {
            const int off = (c + 1) * 16;
            a0 = *(const float4*)(Aptr + off);
            a1 = *(const float4*)(Aptr + off + 4);
            w  = *(const float4*)(Bptr + off);
        }

        // ---- fragments
        uint32_t a[2][4], bh[2][4], bl[2][4];
        ldmx4(bh[0], st + 2 * GA + boff);
        ldmx4(bh[1], st + 2 * GA + boff + 16 * GROW);
        ldmx4(bl[0], st + 2 * GA + GB + boff);
        ldmx4(bl[1], st + 2 * GA + GB + boff + 16 * GROW);
        ldmx4(a[0],  st + aoff);
        ldmx4(a[1],  st + aoff + 16 * GROW);

        // hi*hi + hi*lo
#pragma unroll
        for (int mt = 0; mt < 2; mt++)
#pragma unroll
            for (int g = 0; g < 2; g++) {
                mma16816(acc[mt][g * 2 + 0], a[mt], bh[g][0], bh[g][1]);
                mma16816(acc[mt][g * 2 + 1], a[mt], bh[g][2], bh[g][3]);
                mma16816(acc[mt][g * 2 + 0], a[mt], bl[g][0], bl[g][1]);
                mma16816(acc[mt][g * 2 + 1], a[mt], bl[g][2], bl[g][3]);
            }

        // lo*hi
        ldmx4(a[0], st + GA + aoff);
        ldmx4(a[1], st + GA + aoff + 16 * GROW);
#pragma unroll
        for (int mt = 0; mt < 2; mt++)
#pragma unroll
            for (int g = 0; g < 2; g++) {
                mma16816(acc[mt][g * 2 + 0], a[mt], bh[g][0], bh[g][1]);
                mma16816(acc[mt][g * 2 + 1], a[mt], bh[g][2], bh[g][3]);
            }

        // ---- stage next chunk
        if (c < NC - 1) {
            stage(stg, a0, a1, w);
        }
        __syncthreads();
    }

    // ---- epilogue: D fragment -> global (+bias)
    const int lq = lane >> 2;
    const int lc = (lane & 3) * 2;
#pragma unroll
    for (int mt = 0; mt < 2; mt++) {
#pragma unroll
        for (int g8 = 0; g8 < 4; g8++) {
            const int col = n0 + wn * 32 + g8 * 8 + lc;
            const float bx = bias[col];
            const float by = bias[col + 1];
            const int mr0 = m0 + wm * 32 + mt * 16 + lq;
            const int mr1 = mr0 + 8;
            float2 v0 = make_float2(acc[mt][g8][0] + bx, acc[mt][g8][1] + by);
            float2 v1 = make_float2(acc[mt][g8][2] + bx, acc[mt][g8][3] + by);
            if (MODE == 0) {
                const int h  = col >> 6;
                const int hd = col & 63;
                {
                    const int bb = mr0 >> 11, s = mr0 & 2047;
                    *(float2*)(out + (((size_t)(bb * NHEAD + h)) * S_LEN + s) * HDIM + hd) = v0;
                }
                {
                    const int bb = mr1 >> 11, s = mr1 & 2047;
                    *(float2*)(out + (((size_t)(bb * NHEAD + h)) * S_LEN + s) * HDIM + hd) = v1;
                }
            } else {
                *(float2*)(out + (size_t)mr0 * D_MODEL + col) = v0;
                *(float2*)(out + (size_t)mr1 * D_MODEL + col) = v1;
            }
        }
    }
}

// ---------------------------------------------------------------------------
// Flash attention with HMMA split bf16 (3 terms per GEMM stage).
// Br=128 (8 warps x m16 strip), Bc=64, Hd=64.
// launch_bounds(256,2): 2 CTAs/SM; P packing moved inside the PV k-loop to
// keep live registers under the 128-reg cap.
// ---------------------------------------------------------------------------
#define FROW 144
#define FQH  0
#define FQL  (128 * FROW)
#define FKH  (2 * 128 * FROW)
#define FKL  (FKH + 64 * FROW)
#define FVH  (FKH + 2 * 64 * FROW)
#define FVL  (FKH + 3 * 64 * FROW)
#define FLASH_SMEM (FKH + 4 * 64 * FROW)   // 73728
#define FLOFF (64 * FROW)

__global__ __launch_bounds__(256, 2)
void flash_mma()
{
    extern __shared__ char fsm[];
    const uint32_t sb = smem_u32(fsm);
    const int tid  = threadIdx.x;
    const int lane = tid & 31;
    const int wid  = tid >> 5;          // 0..7, q strip 16*wid
    const int bh   = blockIdx.y;
    const int q0   = blockIdx.x * 128;

    const float* Qb = g_Q + ((size_t)bh * S_LEN + q0) * HDIM;
    const float* Kb = g_K + (size_t)bh * S_LEN * HDIM;
    const float* Vb = g_V + (size_t)bh * S_LEN * HDIM;

    const float SCL = 0.125f * 1.4426950408889634f;   // scale * log2(e)

    // ---- load Q once (scaled), split hi/lo
#pragma unroll
    for (int i = 0; i < 8; i++) {
        const int idx = tid + i * 256;
        const int row = idx >> 4;
        const int c4  = (idx & 15) << 2;
        float4 v = *(const float4*)&Qb[row * HDIM + c4];
        v.x *= SCL; v.y *= SCL; v.z *= SCL; v.w *= SCL;
        split_store(fsm + FQH + row * FROW + c4 * 2,
                    fsm + FQL + row * FROW + c4 * 2, v);
    }

    // ---- ldmatrix base addresses
    const uint32_t aQ = sb + FQH
        + (uint32_t)((16 * wid + (lane & 7) + ((lane >> 3) & 1) * 8) * FROW)
        + ((lane >> 4) & 1) * 16;
    const uint32_t bK = sb + FKH
        + (uint32_t)(((lane & 7) + ((lane >> 4) & 1) * 8) * FROW)
        + ((lane >> 3) & 1) * 16;
    const uint32_t bV = sb + FVH
        + (uint32_t)(((lane & 7) + ((lane >> 3) & 1) * 8) * FROW)
        + ((lane >> 4) & 1) * 16;

    float oA[8][4];
    float mr[2], lr[2];
#pragma unroll
    for (int j = 0; j < 8; j++)
#pragma unroll
        for (int k = 0; k < 4; k++) oA[j][k] = 0.0f;
    mr[0] = mr[1] = -1e30f;
    lr[0] = lr[1] = 0.0f;

    for (int kt = 0; kt < S_LEN / 64; kt++) {
        __syncthreads();   // prior-iter smem reads done (iter 0: Q writes)

        // ---- load K/V tile, split hi/lo
        const float* Kt = Kb + (size_t)kt * 64 * HDIM;
        const float* Vt = Vb + (size_t)kt * 64 * HDIM;
#pragma unroll
        for (int i = 0; i < 4; i++) {
            const int idx = tid + i * 256;
            const int row = idx >> 4;
            const int c4  = (idx & 15) << 2;
            float4 kv = *(const float4*)&Kt[row * HDIM + c4];
            float4 vv = *(const float4*)&Vt[row * HDIM + c4];
            split_store(fsm + FKH + row * FROW + c4 * 2,
                        fsm + FKL + row * FROW + c4 * 2, kv);
            split_store(fsm + FVH + row * FROW + c4 * 2,
                        fsm + FVL + row * FROW + c4 * 2, vv);
        }
        __syncthreads();

        // ---- S = Qh*Kh + Qh*Kl + Ql*Kh  (fp32 accumulators, log2 domain)
        float sA[8][4];
#pragma unroll
        for (int j = 0; j < 8; j++)
#pragma unroll
            for (int k = 0; k < 4; k++) sA[j][k] = 0.0f;

#pragma unroll
        for (int kc = 0; kc < 4; kc++) {
            uint32_t qh[4], ql[4];
            ldmx4(qh, aQ + kc * 32);
            ldmx4(ql, aQ + (FQL - FQH) + kc * 32);
#pragma unroll
            for (int jp = 0; jp < 4; jp++) {
                uint32_t kh[4], kl[4];
                const uint32_t ka = bK + jp * (16 * FROW) + kc * 32;
                ldmx4(kh, ka);
                ldmx4(kl, ka + FLOFF);
                mma16816(sA[2 * jp],     qh, kh[0], kh[1]);
                mma16816(sA[2 * jp + 1], qh, kh[2], kh[3]);
                mma16816(sA[2 * jp],     qh, kl[0], kl[1]);
                mma16816(sA[2 * jp + 1], qh, kl[2], kl[3]);
                mma16816(sA[2 * jp],     ql, kh[0], kh[1]);
                mma16816(sA[2 * jp + 1], ql, kh[2], kh[3]);
            }
        }

        // ---- online softmax on fragments (rows lq, lq+8; quad shfl 1,2)
        float corr[2];
#pragma unroll
        for (int r = 0; r < 2; r++) {
            float mx = -1e30f;
#pragma unroll
            for (int j = 0; j < 8; j++)
                mx = fmaxf(mx, fmaxf(sA[j][2 * r], sA[j][2 * r + 1]));
            mx = fmaxf(mx, __shfl_xor_sync(0xffffffffu, mx, 1));
            mx = fmaxf(mx, __shfl_xor_sync(0xffffffffu, mx, 2));

            const float mn = fmaxf(mr[r], mx);
            corr[r] = ex2f_fast(mr[r] - mn);
            mr[r] = mn;

            float ls = 0.0f;
#pragma unroll
            for (int j = 0; j < 8; j++) {
                const float p0 = ex2f_fast(sA[j][2 * r]     - mn);
                const float p1 = ex2f_fast(sA[j][2 * r + 1] - mn);
                sA[j][2 * r] = p0;
                sA[j][2 * r + 1] = p1;
                ls += p0 + p1;
            }
            ls += __shfl_xor_sync(0xffffffffu, ls, 1);
            ls += __shfl_xor_sync(0xffffffffu, ls, 2);
            lr[r] = lr[r] * corr[r] + ls;
        }

        // ---- rescale O by correction
#pragma unroll
        for (int j = 0; j < 8; j++) {
            oA[j][0] *= corr[0];
            oA[j][1] *= corr[0];
            oA[j][2] *= corr[1];
            oA[j][3] *= corr[1];
        }

        // ---- O += Ph*Vh + Ph*Vl + Pl*Vh  (P packed per k-chunk, low reg use)
#pragma unroll
        for (int kc = 0; kc < 4; kc++) {
            uint32_t ph[4], pl[4];
            pack_hilo(sA[2 * kc][0],     sA[2 * kc][1],     ph[0], pl[0]);
            pack_hilo(sA[2 * kc][2],     sA[2 * kc][3],     ph[1], pl[1]);
            pack_hilo(sA[2 * kc + 1][0], sA[2 * kc + 1][1], ph[2], pl[2]);
            pack_hilo(sA[2 * kc + 1][2], sA[2 * kc + 1][3], ph[3], pl[3]);
#pragma unroll
            for (int hp = 0; hp < 4; hp++) {
                uint32_t vh[4], vl[4];
                const uint32_t va = bV + kc * (16 * FROW) + hp * 32;
                ldmx4t(vh, va);
                ldmx4t(vl, va + FLOFF);
                mma16816(oA[2 * hp],     ph, vh[0], vh[1]);
                mma16816(oA[2 * hp + 1], ph, vh[2], vh[3]);
                mma16816(oA[2 * hp],     ph, vl[0], vl[1]);
                mma16816(oA[2 * hp + 1], ph, vl[2], vl[3]);
                mma16816(oA[2 * hp],     pl, vh[0], vh[1]);
                mma16816(oA[2 * hp + 1], pl, vh[2], vh[3]);
            }
        }
    }

    // ---- epilogue: normalize, write context
    const int b  = bh >> 4;
    const int h  = bh & 15;
    const int lq = lane >> 2;
    const int lc2 = (lane & 3) * 2;
    const float inv0 = 1.0f / lr[0];
    const float inv1 = 1.0f / lr[1];
    const size_t row0 = (size_t)b * S_LEN + q0 + 16 * wid + lq;
#pragma unroll
    for (int j = 0; j < 8; j++) {
        const int col = h * HDIM + 8 * j + lc2;
        *(float2*)&g_C[row0 * D_MODEL + col] =
            make_float2(oA[j][0] * inv0, oA[j][1] * inv0);
        *(float2*)&g_C[(row0 + 8) * D_MODEL + col] =
            make_float2(oA[j][2] * inv1, oA[j][3] * inv1);
    }
}

// ---------------------------------------------------------------------------
// Launch
// ---------------------------------------------------------------------------
extern "C" void kernel_launch(void* const* d_in, const int* in_sizes, int n_in,
                              void* d_out, int out_size)
{
    const float* x  = (const float*)d_in[0];
    const float* Wq = (const float*)d_in[1];
    const float* bq = (const float*)d_in[2];
    const float* Wk = (const float*)d_in[3];
    const float* bk = (const float*)d_in[4];
    const float* Wv = (const float*)d_in[5];
    const float* bv = (const float*)d_in[6];
    const float* Wo = (const float*)d_in[7];
    const float* bo = (const float*)d_in[8];
    float* out = (float*)d_out;

    cudaFuncSetAttribute(flash_mma,
                         cudaFuncAttributeMaxDynamicSharedMemorySize, FLASH_SMEM);
    cudaFuncSetAttribute(gemm_mma<0>,
                         cudaFuncAttributeMaxDynamicSharedMemorySize, GEMM_SMEM);
    cudaFuncSetAttribute(gemm_mma<1>,
                         cudaFuncAttributeMaxDynamicSharedMemorySize, GEMM_SMEM);

    // 1) fused QKV projections (HMMA bf16 split)
    {
        dim3 grid(D_MODEL / 64, M_ROWS / 128, 3);
        gemm_mma<0><<<grid, 256, GEMM_SMEM>>>(x, Wq, Wk, Wv, bq, bk, bv, nullptr);
    }
    // 2) flash attention (HMMA bf16 split)
    {
        dim3 grid(S_LEN / 128, BATCH * NHEAD);
        flash_mma<<<grid, 256, FLASH_SMEM>>>();
    }
    // 3) output projection (HMMA bf16 split)
    {
        dim3 grid(D_MODEL / 64, M_ROWS / 128, 1);
        gemm_mma<1><<<grid, 256, GEMM_SMEM>>>(nullptr, Wo, nullptr, nullptr,
                                              bo, nullptr, nullptr, out);
    }
}